// round 3
// baseline (speedup 1.0000x reference)
#include <cuda_runtime.h>
#include <math.h>

// Problem constants
static const int Bsz = 4;
static const int T   = 2048;
static const int E   = 128;
static const int H   = 8;
static const int D   = 1024;   // H*E
static const int F   = 4096;   // 4*D
static const int BT  = Bsz * T;   // 8192
static const int BH  = Bsz * H;   // 32

// Scratch (device globals — no allocation allowed)
__device__ float g_xn [BT * E];              // 4  MB
__device__ float g_q  [BH * T * E];          // 32 MB
__device__ float g_k  [BH * T * E];          // 32 MB
__device__ float g_v  [BH * T * E];          // 32 MB
__device__ float g_s  [134217728];           // BH*T*T = 512 MB
__device__ float g_att[BH * T * E];          // 32 MB
__device__ float g_hn [BT * D];              // 32 MB
__device__ float g_mid[BT * F];              // 128 MB

typedef unsigned long long u64;

// ---- packed f32x2 helpers (FFMA2 path, only reachable via PTX) ----
__device__ __forceinline__ u64 pk2(float lo, float hi) {
    u64 r;
    asm("mov.b64 %0, {%1, %2};" : "=l"(r)
        : "r"(__float_as_uint(lo)), "r"(__float_as_uint(hi)));
    return r;
}
__device__ __forceinline__ void upk2(u64 v, float& lo, float& hi) {
    unsigned a, b;
    asm("mov.b64 {%0, %1}, %2;" : "=r"(a), "=r"(b) : "l"(v));
    lo = __uint_as_float(a); hi = __uint_as_float(b);
}
__device__ __forceinline__ void fma2(u64& d, u64 a, u64 b) {
    asm("fma.rn.f32x2 %0, %1, %2, %0;" : "+l"(d) : "l"(a), "l"(b));
}

__device__ __forceinline__ float gelu_exact(float x) {
    return 0.5f * x * (1.0f + erff(x * 0.70710678118654752440f));
}

// ============================================================================
// Generic tiled fp32 GEMM with f32x2 packed accumulation.
//   C[bz] = alpha * A[bz] @ (TB ? B[bz]^T : B[bz]) (+ bias) (EPI==1: gelu)
// A: row-major [M,K]. B: row-major [K,N] (TB=false) or [N,K] (TB=true).
// Batch addressing: Ab = A + (bz/divA)*sA ; Bb/bias via (bz%modB) ; Cb = C + bz*sC.
// causal==1 : skip block if entire row-range < col-range (scores, upper tri)
// causal==2 : clamp K loop to m0+BM (AV: attn[t,s]==0 for s>t)
// Requirements: M%BM==0, N%BN==0, K%BK==0, BM*2==NT, BN*2==NT, BK*(BN/4)==NT,
//               TM%4==0, TN%2==0.
// ============================================================================
template<int BM, int BN, int BK, int TM, int TN, bool TB, int EPI>
__global__ void __launch_bounds__((BM/TM)*(BN/TN))
gemm_f32(const float* __restrict__ A, const float* __restrict__ Bm,
         const float* __restrict__ bias, float* __restrict__ C,
         int M, int N, int K,
         int divA, long sA, int modB, long sB, long sBias, long sC,
         float alpha, int causal)
{
    __shared__ float As[BK][BM];
    __shared__ float Bs[BK][BN];

    const int tid = threadIdx.x;
    const int m0  = blockIdx.y * BM;
    const int n0  = blockIdx.x * BN;
    const int bz  = blockIdx.z;

    if (causal == 1 && (m0 + BM) <= n0) return;   // fully masked block

    const float* Ab = A + (long)(bz / divA) * sA + (long)m0 * K;
    const float* Bb = Bm + (long)(bz % modB) * sB;
    if (TB) Bb += (long)n0 * K; else Bb += n0;
    float* Cb = C + (long)bz * sC + (long)m0 * N + n0;

    int kEnd = K;
    if (causal == 2) { int ke = m0 + BM; kEnd = (ke < K) ? ke : K; }

    const int arow = tid >> 1;          // < BM (== BN) rows
    const int acol = (tid & 1) * 4;
    const int tx   = tid % (BN / TN);
    const int ty   = tid / (BN / TN);

    u64 acc[TM][TN/2];
    #pragma unroll
    for (int i = 0; i < TM; i++)
        #pragma unroll
        for (int j = 0; j < TN/2; j++) acc[i][j] = 0ull;

    for (int k0 = 0; k0 < kEnd; k0 += BK) {
        {   // A tile (transposed store into smem)
            float4 v = *(const float4*)(Ab + (long)arow * K + k0 + acol);
            As[acol+0][arow] = v.x; As[acol+1][arow] = v.y;
            As[acol+2][arow] = v.z; As[acol+3][arow] = v.w;
        }
        if (TB) {
            float4 v = *(const float4*)(Bb + (long)arow * K + k0 + acol);
            Bs[acol+0][arow] = v.x; Bs[acol+1][arow] = v.y;
            Bs[acol+2][arow] = v.z; Bs[acol+3][arow] = v.w;
        } else {
            const int brow = tid / (BN/4);
            const int bcol = (tid % (BN/4)) * 4;
            float4 v = *(const float4*)(Bb + (long)(k0 + brow) * N + bcol);
            *(float4*)&Bs[brow][bcol] = v;
        }
        __syncthreads();

        #pragma unroll
        for (int kk = 0; kk < BK; kk++) {
            u64 a2[TM];
            const float4* ap = (const float4*)&As[kk][ty * TM];
            #pragma unroll
            for (int i4 = 0; i4 < TM/4; i4++) {
                float4 av = ap[i4];
                a2[i4*4+0] = pk2(av.x, av.x);
                a2[i4*4+1] = pk2(av.y, av.y);
                a2[i4*4+2] = pk2(av.z, av.z);
                a2[i4*4+3] = pk2(av.w, av.w);
            }
            u64 b2[TN/2];
            const float2* bp = (const float2*)&Bs[kk][tx * TN];
            #pragma unroll
            for (int j = 0; j < TN/2; j++) {
                float2 bv = bp[j];
                b2[j] = pk2(bv.x, bv.y);
            }
            #pragma unroll
            for (int i = 0; i < TM; i++)
                #pragma unroll
                for (int j = 0; j < TN/2; j++)
                    fma2(acc[i][j], a2[i], b2[j]);
        }
        __syncthreads();
    }

    const float* biasp = bias ? (bias + (long)(bz % modB) * sBias + n0 + tx * TN)
                              : (const float*)0;
    #pragma unroll
    for (int i = 0; i < TM; i++) {
        float* crow = Cb + (long)(ty * TM + i) * N + tx * TN;
        #pragma unroll
        for (int j = 0; j < TN/2; j++) {
            float lo, hi;
            upk2(acc[i][j], lo, hi);
            lo *= alpha; hi *= alpha;
            if (biasp) { lo += biasp[2*j]; hi += biasp[2*j+1]; }
            if (EPI == 1) { lo = gelu_exact(lo); hi = gelu_exact(hi); }
            *(float2*)&crow[2*j] = make_float2(lo, hi);
        }
    }
}

// ============================================================================
// LayerNorm over E=128 (one block per row, 128 threads)
// ============================================================================
__global__ void ln_e128(const float* __restrict__ X, const float* __restrict__ g,
                        const float* __restrict__ b, float* __restrict__ O)
{
    const int row = blockIdx.x;
    const int tid = threadIdx.x;
    float x = X[(size_t)row * 128 + tid];
    float s1 = x, s2 = x * x;
    #pragma unroll
    for (int o = 16; o > 0; o >>= 1) {
        s1 += __shfl_xor_sync(0xffffffffu, s1, o);
        s2 += __shfl_xor_sync(0xffffffffu, s2, o);
    }
    __shared__ float r1[4], r2[4];
    if ((tid & 31) == 0) { r1[tid >> 5] = s1; r2[tid >> 5] = s2; }
    __syncthreads();
    s1 = r1[0] + r1[1] + r1[2] + r1[3];
    s2 = r2[0] + r2[1] + r2[2] + r2[3];
    float mu  = s1 * (1.0f / 128.0f);
    float var = s2 * (1.0f / 128.0f) - mu * mu;
    float rs  = rsqrtf(var + 1e-5f);
    O[(size_t)row * 128 + tid] = (x - mu) * rs * g[tid] + b[tid];
}

// ============================================================================
// Gather heads [B,H,T,E] -> [B,T,D] + LayerNorm over D=1024
// (one block per (b,t), 256 threads x 4 elems)
// ============================================================================
__global__ void ln_gather(const float* __restrict__ att, const float* __restrict__ g,
                          const float* __restrict__ b, float* __restrict__ O)
{
    const int row = blockIdx.x;         // b*T + t
    const int bb  = row >> 11;
    const int t   = row & 2047;
    const int tid = threadIdx.x;
    const int d0  = tid * 4;
    const int h   = d0 >> 7;
    const int e   = d0 & 127;

    float4 v = *(const float4*)&att[((size_t)(bb * H + h) * T + t) * E + e];
    float s1 = v.x + v.y + v.z + v.w;
    float s2 = v.x*v.x + v.y*v.y + v.z*v.z + v.w*v.w;
    #pragma unroll
    for (int o = 16; o > 0; o >>= 1) {
        s1 += __shfl_xor_sync(0xffffffffu, s1, o);
        s2 += __shfl_xor_sync(0xffffffffu, s2, o);
    }
    __shared__ float r1[8], r2[8];
    if ((tid & 31) == 0) { r1[tid >> 5] = s1; r2[tid >> 5] = s2; }
    __syncthreads();
    s1 = 0.f; s2 = 0.f;
    #pragma unroll
    for (int i = 0; i < 8; i++) { s1 += r1[i]; s2 += r2[i]; }
    float mu  = s1 * (1.0f / 1024.0f);
    float var = s2 * (1.0f / 1024.0f) - mu * mu;
    float rs  = rsqrtf(var + 1e-5f);

    float4 gg = *(const float4*)&g[d0];
    float4 bv = *(const float4*)&b[d0];
    float4 o;
    o.x = (v.x - mu) * rs * gg.x + bv.x;
    o.y = (v.y - mu) * rs * gg.y + bv.y;
    o.z = (v.z - mu) * rs * gg.z + bv.z;
    o.w = (v.w - mu) * rs * gg.w + bv.w;
    *(float4*)&O[(size_t)row * 1024 + d0] = o;
}

// ============================================================================
// Column softmax over the QUERY axis t (scores[t][s], softmax over t for each s),
// restricted to the causal-valid range t >= s; writes exact 0 for t < s.
// One thread per column s; warps stream rows -> coalesced.
// ============================================================================
__global__ void colsoftmax(float* __restrict__ S)
{
    const int z  = blockIdx.y;
    float* P = S + (size_t)z * T * T;
    const int s0 = blockIdx.x * blockDim.x;
    const int s  = s0 + threadIdx.x;

    float m = -3.4e38f;
    for (int t = s0; t < T; ++t) {
        float v = P[(size_t)t * T + s];
        if (t >= s) m = fmaxf(m, v);
    }
    float sum = 0.f;
    for (int t = s0; t < T; ++t) {
        float v = P[(size_t)t * T + s];
        if (t >= s) sum += __expf(v - m);
    }
    float inv = 1.0f / sum;
    for (int t = 0; t < T; ++t) {
        float o = 0.0f;
        if (t >= s) o = __expf(P[(size_t)t * T + s] - m) * inv;
        P[(size_t)t * T + s] = o;
    }
}

// ============================================================================
// Host launcher
// ============================================================================
extern "C" void kernel_launch(void* const* d_in, const int* in_sizes, int n_in,
                              void* d_out, int out_size)
{
    const float* X    = (const float*)d_in[0];
    const float* ln1g = (const float*)d_in[1];
    const float* ln1b = (const float*)d_in[2];
    const float* Wq   = (const float*)d_in[3];
    const float* bq   = (const float*)d_in[4];
    const float* Wk   = (const float*)d_in[5];
    const float* bk   = (const float*)d_in[6];
    const float* Wv   = (const float*)d_in[7];
    const float* bv   = (const float*)d_in[8];
    const float* ln2g = (const float*)d_in[9];
    const float* ln2b = (const float*)d_in[10];
    const float* W1   = (const float*)d_in[11];
    const float* b1   = (const float*)d_in[12];
    const float* W2   = (const float*)d_in[13];
    const float* b2   = (const float*)d_in[14];
    float* out = (float*)d_out;

    float *xn, *q, *k, *v, *s, *att, *hn, *mid;
    cudaGetSymbolAddress((void**)&xn,  g_xn);
    cudaGetSymbolAddress((void**)&q,   g_q);
    cudaGetSymbolAddress((void**)&k,   g_k);
    cudaGetSymbolAddress((void**)&v,   g_v);
    cudaGetSymbolAddress((void**)&s,   g_s);
    cudaGetSymbolAddress((void**)&att, g_att);
    cudaGetSymbolAddress((void**)&hn,  g_hn);
    cudaGetSymbolAddress((void**)&mid, g_mid);

    // 1. LN1
    ln_e128<<<BT, 128>>>(X, ln1g, ln1b, xn);

    // 2. QKV projections: per (b,h): [T,E] @ [E,E] + bias
    dim3 gqkv(1, T / 128, BH);
    gemm_f32<128,128,8,8,8,false,0><<<gqkv, 256>>>(
        xn, Wq, bq, q, T, E, E, H, (long)T*E, H, (long)E*E, (long)E, (long)T*E, 1.0f, 0);
    gemm_f32<128,128,8,8,8,false,0><<<gqkv, 256>>>(
        xn, Wk, bk, k, T, E, E, H, (long)T*E, H, (long)E*E, (long)E, (long)T*E, 1.0f, 0);
    gemm_f32<128,128,8,8,8,false,0><<<gqkv, 256>>>(
        xn, Wv, bv, v, T, E, E, H, (long)T*E, H, (long)E*E, (long)E, (long)T*E, 1.0f, 0);

    // 3. scores = q @ k^T / sqrt(E) (skip fully-masked upper-tri blocks)
    dim3 gsc(T / 128, T / 128, BH);
    gemm_f32<128,128,8,8,8,true,0><<<gsc, 256>>>(
        q, k, (const float*)0, s, T, T, E, 1, (long)T*E, BH, (long)T*E, 0, (long)T*T,
        0.08838834764831843f, 1);

    // 4. softmax over query axis (columns), zeros in masked region
    colsoftmax<<<dim3(T / 256, BH), 256>>>(s);

    // 5. out = attn @ v (K-loop clamped causally)
    dim3 gav(1, T / 128, BH);
    gemm_f32<128,128,8,8,8,false,0><<<gav, 256>>>(
        s, v, (const float*)0, att, T, E, T, 1, (long)T*T, BH, (long)T*E, 0, (long)T*E,
        1.0f, 2);

    // 6. concat heads + LN2
    ln_gather<<<BT, 256>>>(att, ln2g, ln2b, hn);

    // 7. MLP1: [8192,1024] @ [1024,4096] + b1, exact GELU
    dim3 g1(F / 128, BT / 128, 1);
    gemm_f32<128,128,8,8,8,false,1><<<g1, 256>>>(
        hn, W1, b1, mid, BT, F, D, 1, 0, 1, 0, 0, 0, 1.0f, 0);

    // 8. MLP2: [8192,4096] @ [4096,128] + b2 -> out (64x64 tiles for grid coverage)
    dim3 g2(E / 64, BT / 64, 1);
    gemm_f32<64,64,8,8,4,false,0><<<g2, 128>>>(
        mid, W2, b2, out, BT, E, F, 1, 0, 1, 0, 0, 0, 1.0f, 0);
}

// round 7
// speedup vs baseline: 2.0414x; 2.0414x over previous
#include <cuda_runtime.h>
#include <cuda_bf16.h>
#include <math.h>
#include <stdint.h>

#define Bsz 4
#define T   2048
#define E   128
#define H   8
#define DD  1024
#define FF  4096
#define BT  8192
#define BH  32

typedef __nv_bfloat16 bf;

// ---------------- scratch (device globals; no allocation allowed) -----------
__device__ __align__(16) bf    g_xnh[BT*E],  g_xnl[BT*E];
__device__ __align__(16) bf    g_wqth[H*E*E], g_wqtl[H*E*E];
__device__ __align__(16) bf    g_wkth[H*E*E], g_wktl[H*E*E];
__device__ __align__(16) bf    g_wvth[H*E*E], g_wvtl[H*E*E];
__device__ __align__(16) bf    g_qh[BH*T*E], g_ql[BH*T*E];
__device__ __align__(16) bf    g_kh[BH*T*E], g_kl[BH*T*E];
__device__ __align__(16) float g_v [BH*T*E];
__device__ __align__(16) bf    g_vth[BH*E*T], g_vtl[BH*E*T];
__device__ __align__(16) float g_s [134217728];               // BH*T*T fp32
__device__ __align__(16) bf    g_ath[134217728], g_atl[134217728];
__device__ __align__(16) float g_att[BH*T*E];
__device__ __align__(16) bf    g_hnh[BT*DD], g_hnl[BT*DD];
__device__ __align__(16) bf    g_w1th[FF*DD], g_w1tl[FF*DD];
__device__ __align__(16) bf    g_w2th[E*FF],  g_w2tl[E*FF];
__device__ __align__(16) bf    g_midh[(size_t)BT*FF], g_midl[(size_t)BT*FF];

// ---------------- helpers ---------------------------------------------------
__device__ __forceinline__ uint32_t smem_u32(const void* p) {
    uint32_t a;
    asm("{ .reg .u64 t; cvta.to.shared.u64 t, %1; cvt.u32.u64 %0, t; }"
        : "=r"(a) : "l"(p));
    return a;
}
__device__ __forceinline__ void cpa16(uint32_t dst, const void* src) {
    asm volatile("cp.async.cg.shared.global [%0], [%1], 16;"
                 :: "r"(dst), "l"(src) : "memory");
}
__device__ __forceinline__ void ldm4(uint32_t* r, uint32_t addr) {
    asm volatile("ldmatrix.sync.aligned.m8n8.x4.shared.b16 {%0,%1,%2,%3}, [%4];"
                 : "=r"(r[0]), "=r"(r[1]), "=r"(r[2]), "=r"(r[3]) : "r"(addr));
}
__device__ __forceinline__ void mma16816(float* c, const uint32_t* a, const uint32_t* b) {
    asm volatile(
        "mma.sync.aligned.m16n8k16.row.col.f32.bf16.bf16.f32 "
        "{%0,%1,%2,%3}, {%4,%5,%6,%7}, {%8,%9}, {%0,%1,%2,%3};\n"
        : "+f"(c[0]), "+f"(c[1]), "+f"(c[2]), "+f"(c[3])
        : "r"(a[0]), "r"(a[1]), "r"(a[2]), "r"(a[3]), "r"(b[0]), "r"(b[1]));
}
__device__ __forceinline__ void split_bf16(float x, bf& h, bf& l) {
    h = __float2bfloat16_rn(x);
    l = __float2bfloat16_rn(x - __bfloat162float(h));
}
__device__ __forceinline__ unsigned pack2(bf a, bf b) {
    return (unsigned)__bfloat16_as_ushort(a) | ((unsigned)__bfloat16_as_ushort(b) << 16);
}
__device__ __forceinline__ float gelu_exact(float x) {
    return 0.5f * x * (1.0f + erff(x * 0.70710678118654752440f));
}

// ============================================================================
// Split-bf16 HMMA GEMM (mma.sync m16n8k16, fp32 accum).
//   C[128x128 tile] = alpha * (A @ B^T) (+bias) (EPI==1: gelu)
//  A: [M,K] K-major split bf16 (Ah,Al);  B: [N,K] K-major split bf16 (Bh,Bl)
//  OUTS: 0 -> fp32 C ; 1 -> split bf16 (Ch,Cl)
//  CAUSAL: 0 none, 1 skip block when m0+128<=n0, 2 clamp K to m0+128
//  batch z: A += (z/divA)*sA ; B,bias += (z%modB)*sB/sBias ; C += z*sC
//  K (and kEnd) multiples of 32; M,N multiples of 128.
// Smem tile layout: [stage][mat][row][col] rows padded to 40 bf16 (80B):
// the 8 ldmatrix row segments land on all 8 distinct 16B groups -> no conflicts.
// ============================================================================
#define GEMM_SMEM (2 * 4 * 128 * 40 * 2)   // 81920 bytes

template<int EPI, int OUTS, int CAUSAL>
__global__ void __launch_bounds__(256, 1) gemm_mma(
    const bf* __restrict__ Ahg, const bf* __restrict__ Alg,
    const bf* __restrict__ Bhg, const bf* __restrict__ Blg,
    const float* __restrict__ bias,
    float* __restrict__ C, bf* __restrict__ Ch, bf* __restrict__ Cl,
    int N, int K, int divA, long sA, int modB, long sB, long sBias, long sC,
    float alpha)
{
    extern __shared__ __align__(16) bf sm[];
    const int tid  = threadIdx.x;
    const int wid  = tid >> 5, lane = tid & 31;
    const int wm   = wid & 1;            // warp row (2)  -> 64 rows
    const int wn   = wid >> 1;           // warp col (4)  -> 32 cols
    const int m0   = blockIdx.y * 128, n0 = blockIdx.x * 128, bz = blockIdx.z;
    if (CAUSAL == 1 && m0 + 128 <= n0) return;

    const uint32_t sbase = smem_u32(sm);

    const bf* A0 = Ahg + (long)(bz / divA) * sA + (long)m0 * K;
    const bf* A1 = Alg + (long)(bz / divA) * sA + (long)m0 * K;
    const bf* B0 = Bhg + (long)(bz % modB) * sB + (long)n0 * K;
    const bf* B1 = Blg + (long)(bz % modB) * sB + (long)n0 * K;

    int kEnd = K;
    if (CAUSAL == 2) { int ke = m0 + 128; kEnd = ke < K ? ke : K; }
    const int nch = kEnd >> 5;           // chunks of 32

    auto loadStage = [&](int st, int k0) {
        #pragma unroll
        for (int i = 0; i < 8; ++i) {
            int idx = tid + i * 256;     // 0..2047
            int mat = idx >> 9;
            int rem = idx & 511;
            int row = rem >> 2;
            int seg = rem & 3;
            const bf* src = (mat == 0 ? A0 : mat == 1 ? A1 : mat == 2 ? B0 : B1)
                            + (long)row * K + k0 + seg * 8;
            uint32_t dst = sbase + (uint32_t)((((mat)*128 + row) * 40 + seg * 8) * 2)
                                 + (uint32_t)(st * 40960);
            cpa16(dst, src);
        }
        asm volatile("cp.async.commit_group;" ::: "memory");
    };

    float acc[4][4][4];
    #pragma unroll
    for (int a = 0; a < 4; ++a)
        #pragma unroll
        for (int b = 0; b < 4; ++b)
            #pragma unroll
            for (int c = 0; c < 4; ++c) acc[a][b][c] = 0.f;

    loadStage(0, 0);

    const int lm = lane & 15, lk = lane >> 4;            // A ldmatrix addr
    const int bn = (lane & 7) | ((lane >> 1) & 8);       // B: lane%8 + 8*(lane/16)
    const int bk = (lane >> 3) & 1;

    for (int c = 0; c < nch; ++c) {
        int st = c & 1;
        if (c + 1 < nch) {
            loadStage(st ^ 1, (c + 1) << 5);
            asm volatile("cp.async.wait_group 1;" ::: "memory");
        } else {
            asm volatile("cp.async.wait_group 0;" ::: "memory");
        }
        __syncthreads();

        const uint32_t stb = sbase + (uint32_t)(st * 40960);
        #pragma unroll
        for (int ks = 0; ks < 32; ks += 16) {
            uint32_t ah[4][4], al[4][4], bh[2][4], bl[2][4];
            #pragma unroll
            for (int mt = 0; mt < 4; ++mt) {
                int row = wm * 64 + mt * 16 + lm, col = ks + lk * 8;
                ldm4(ah[mt], stb + (uint32_t)(((0 * 128 + row) * 40 + col) * 2));
                ldm4(al[mt], stb + (uint32_t)(((1 * 128 + row) * 40 + col) * 2));
            }
            #pragma unroll
            for (int p = 0; p < 2; ++p) {
                int row = wn * 32 + p * 16 + bn, col = ks + bk * 8;
                ldm4(bh[p], stb + (uint32_t)(((2 * 128 + row) * 40 + col) * 2));
                ldm4(bl[p], stb + (uint32_t)(((3 * 128 + row) * 40 + col) * 2));
            }
            #pragma unroll
            for (int mt = 0; mt < 4; ++mt)
                #pragma unroll
                for (int nt = 0; nt < 4; ++nt) {
                    const uint32_t* Bh = &bh[nt >> 1][(nt & 1) * 2];
                    const uint32_t* Bl = &bl[nt >> 1][(nt & 1) * 2];
                    mma16816(acc[mt][nt], ah[mt], Bh);
                    mma16816(acc[mt][nt], ah[mt], Bl);
                    mma16816(acc[mt][nt], al[mt], Bh);
                }
        }
        __syncthreads();
    }

    // ------------------------- epilogue -------------------------
    const int l4 = lane >> 2, l2 = (lane & 3) * 2;
    const float* bp = bias ? bias + (long)(bz % modB) * sBias : (const float*)0;
    #pragma unroll
    for (int mt = 0; mt < 4; ++mt) {
        #pragma unroll
        for (int nt = 0; nt < 4; ++nt) {
            int col = n0 + wn * 32 + nt * 8 + l2;
            float b0 = 0.f, b1 = 0.f;
            if (bp) { b0 = __ldg(&bp[col]); b1 = __ldg(&bp[col + 1]); }
            #pragma unroll
            for (int hrow = 0; hrow < 2; ++hrow) {
                int r = m0 + wm * 64 + mt * 16 + hrow * 8 + l4;
                float v0 = acc[mt][nt][hrow * 2 + 0] * alpha + b0;
                float v1 = acc[mt][nt][hrow * 2 + 1] * alpha + b1;
                if (EPI == 1) { v0 = gelu_exact(v0); v1 = gelu_exact(v1); }
                long off = (long)bz * sC + (long)r * N + col;
                if (OUTS == 0) {
                    *(float2*)(C + off) = make_float2(v0, v1);
                } else {
                    bf h0, l0, h1, l1;
                    split_bf16(v0, h0, l0);
                    split_bf16(v1, h1, l1);
                    *(unsigned*)(Ch + off) = pack2(h0, h1);
                    *(unsigned*)(Cl + off) = pack2(l0, l1);
                }
            }
        }
    }
}

// ============================================================================
// LayerNorm over E=128 -> split bf16 out
// ============================================================================
__global__ void ln_e128_split(const float* __restrict__ X, const float* __restrict__ g,
                              const float* __restrict__ b,
                              bf* __restrict__ Oh, bf* __restrict__ Ol)
{
    const int row = blockIdx.x, tid = threadIdx.x;
    float x = X[(size_t)row * 128 + tid];
    float s1 = x, s2 = x * x;
    #pragma unroll
    for (int o = 16; o > 0; o >>= 1) {
        s1 += __shfl_xor_sync(0xffffffffu, s1, o);
        s2 += __shfl_xor_sync(0xffffffffu, s2, o);
    }
    __shared__ float r1[4], r2[4];
    if ((tid & 31) == 0) { r1[tid >> 5] = s1; r2[tid >> 5] = s2; }
    __syncthreads();
    s1 = r1[0] + r1[1] + r1[2] + r1[3];
    s2 = r2[0] + r2[1] + r2[2] + r2[3];
    float mu  = s1 * (1.0f / 128.0f);
    float var = s2 * (1.0f / 128.0f) - mu * mu;
    float rs  = rsqrtf(var + 1e-5f);
    float o = (x - mu) * rs * g[tid] + b[tid];
    bf h, l; split_bf16(o, h, l);
    Oh[(size_t)row * 128 + tid] = h;
    Ol[(size_t)row * 128 + tid] = l;
}

// ============================================================================
// Gather heads [B,H,T,E] -> [B,T,D] + LayerNorm over D=1024 -> split bf16
// ============================================================================
__global__ void ln_gather_split(const float* __restrict__ att, const float* __restrict__ g,
                                const float* __restrict__ b,
                                bf* __restrict__ Oh, bf* __restrict__ Ol)
{
    const int row = blockIdx.x;
    const int bb = row >> 11, t = row & 2047;
    const int tid = threadIdx.x;
    const int d0 = tid * 4, h = d0 >> 7, e = d0 & 127;

    float4 v = *(const float4*)&att[((size_t)(bb * H + h) * T + t) * E + e];
    float s1 = v.x + v.y + v.z + v.w;
    float s2 = v.x*v.x + v.y*v.y + v.z*v.z + v.w*v.w;
    #pragma unroll
    for (int o = 16; o > 0; o >>= 1) {
        s1 += __shfl_xor_sync(0xffffffffu, s1, o);
        s2 += __shfl_xor_sync(0xffffffffu, s2, o);
    }
    __shared__ float r1[8], r2[8];
    if ((tid & 31) == 0) { r1[tid >> 5] = s1; r2[tid >> 5] = s2; }
    __syncthreads();
    s1 = 0.f; s2 = 0.f;
    #pragma unroll
    for (int i = 0; i < 8; i++) { s1 += r1[i]; s2 += r2[i]; }
    float mu  = s1 * (1.0f / 1024.0f);
    float var = s2 * (1.0f / 1024.0f) - mu * mu;
    float rs  = rsqrtf(var + 1e-5f);

    float4 gg = *(const float4*)&g[d0];
    float4 bv = *(const float4*)&b[d0];
    float o0 = (v.x - mu) * rs * gg.x + bv.x;
    float o1 = (v.y - mu) * rs * gg.y + bv.y;
    float o2 = (v.z - mu) * rs * gg.z + bv.z;
    float o3 = (v.w - mu) * rs * gg.w + bv.w;
    bf h0,l0,h1,l1,h2,l2,h3,l3;
    split_bf16(o0,h0,l0); split_bf16(o1,h1,l1);
    split_bf16(o2,h2,l2); split_bf16(o3,h3,l3);
    size_t off = (size_t)row * 1024 + d0;
    *(uint2*)&Oh[off] = make_uint2(pack2(h0,h1), pack2(h2,h3));
    *(uint2*)&Ol[off] = make_uint2(pack2(l0,l1), pack2(l2,l3));
}

// ============================================================================
// Transpose + split:  in fp32 [z][R][Cc]  ->  out split bf16 [z][Cc][R]
// grid (Cc/32, R/32, z), block (32,8)
// ============================================================================
__global__ void transpose_split(const float* __restrict__ in,
                                bf* __restrict__ oh, bf* __restrict__ ol,
                                int R, int Cc)
{
    __shared__ float tle[32][33];
    int z = blockIdx.z;
    const float* ip = in + (size_t)z * R * Cc;
    size_t ob = (size_t)z * R * Cc;
    int r0 = blockIdx.y * 32, c0 = blockIdx.x * 32;
    int tx = threadIdx.x, ty = threadIdx.y;
    #pragma unroll
    for (int i = ty; i < 32; i += 8)
        tle[i][tx] = ip[(size_t)(r0 + i) * Cc + c0 + tx];
    __syncthreads();
    #pragma unroll
    for (int i = ty; i < 32; i += 8) {
        float v = tle[tx][i];
        bf h, l; split_bf16(v, h, l);
        size_t o = ob + (size_t)(c0 + i) * R + r0 + tx;
        oh[o] = h; ol[o] = l;
    }
}

// ============================================================================
// Softmax over the QUERY axis t (per column s), causal region t >= s.
// Single online read pass (max+sum), then exp/normalize write pass.
// Writes split-bf16 attn; zeros cover the band t in [s-127, s) that AV reads.
// ============================================================================
__global__ void colsoftmax(const float* __restrict__ S,
                           bf* __restrict__ Oh, bf* __restrict__ Ol)
{
    int z = blockIdx.y;
    const float* P = S + (size_t)z * T * T;
    bf* oh = Oh + (size_t)z * T * T;
    bf* ol = Ol + (size_t)z * T * T;
    int s = blockIdx.x * blockDim.x + threadIdx.x;

    float m = -3.4e38f, sum = 0.f;
    for (int t = s; t < T; ++t) {
        float v = P[(size_t)t * T + s];
        if (v <= m) {
            sum += __expf(v - m);
        } else {
            sum = sum * __expf(m - v) + 1.0f;
            m = v;
        }
    }
    float inv = 1.0f / sum;
    int t0 = s - 127; if (t0 < 0) t0 = 0;
    for (int t = t0; t < T; ++t) {
        float o = 0.0f;
        if (t >= s) o = __expf(P[(size_t)t * T + s] - m) * inv;
        bf h, l; split_bf16(o, h, l);
        oh[(size_t)t * T + s] = h;
        ol[(size_t)t * T + s] = l;
    }
}

// ============================================================================
// Host launcher
// ============================================================================
extern "C" void kernel_launch(void* const* d_in, const int* in_sizes, int n_in,
                              void* d_out, int out_size)
{
    const float* X    = (const float*)d_in[0];
    const float* ln1g = (const float*)d_in[1];
    const float* ln1b = (const float*)d_in[2];
    const float* Wq   = (const float*)d_in[3];
    const float* bq   = (const float*)d_in[4];
    const float* Wk   = (const float*)d_in[5];
    const float* bk   = (const float*)d_in[6];
    const float* Wv   = (const float*)d_in[7];
    const float* bv   = (const float*)d_in[8];
    const float* ln2g = (const float*)d_in[9];
    const float* ln2b = (const float*)d_in[10];
    const float* W1   = (const float*)d_in[11];
    const float* b1   = (const float*)d_in[12];
    const float* W2   = (const float*)d_in[13];
    const float* b2   = (const float*)d_in[14];
    float* out = (float*)d_out;

    bf *xnh,*xnl,*wqth,*wqtl,*wkth,*wktl,*wvth,*wvtl,*qh,*ql,*kh,*kl;
    bf *vth,*vtl,*ath,*atl,*hnh,*hnl,*w1th,*w1tl,*w2th,*w2tl,*midh,*midl;
    float *v, *s, *att;
    cudaGetSymbolAddress((void**)&xnh, g_xnh);   cudaGetSymbolAddress((void**)&xnl, g_xnl);
    cudaGetSymbolAddress((void**)&wqth, g_wqth); cudaGetSymbolAddress((void**)&wqtl, g_wqtl);
    cudaGetSymbolAddress((void**)&wkth, g_wkth); cudaGetSymbolAddress((void**)&wktl, g_wktl);
    cudaGetSymbolAddress((void**)&wvth, g_wvth); cudaGetSymbolAddress((void**)&wvtl, g_wvtl);
    cudaGetSymbolAddress((void**)&qh, g_qh);     cudaGetSymbolAddress((void**)&ql, g_ql);
    cudaGetSymbolAddress((void**)&kh, g_kh);     cudaGetSymbolAddress((void**)&kl, g_kl);
    cudaGetSymbolAddress((void**)&v, g_v);
    cudaGetSymbolAddress((void**)&vth, g_vth);   cudaGetSymbolAddress((void**)&vtl, g_vtl);
    cudaGetSymbolAddress((void**)&s, g_s);
    cudaGetSymbolAddress((void**)&ath, g_ath);   cudaGetSymbolAddress((void**)&atl, g_atl);
    cudaGetSymbolAddress((void**)&att, g_att);
    cudaGetSymbolAddress((void**)&hnh, g_hnh);   cudaGetSymbolAddress((void**)&hnl, g_hnl);
    cudaGetSymbolAddress((void**)&w1th, g_w1th); cudaGetSymbolAddress((void**)&w1tl, g_w1tl);
    cudaGetSymbolAddress((void**)&w2th, g_w2th); cudaGetSymbolAddress((void**)&w2tl, g_w2tl);
    cudaGetSymbolAddress((void**)&midh, g_midh); cudaGetSymbolAddress((void**)&midl, g_midl);

    cudaFuncSetAttribute(gemm_mma<0,1,0>, cudaFuncAttributeMaxDynamicSharedMemorySize, GEMM_SMEM);
    cudaFuncSetAttribute(gemm_mma<0,0,0>, cudaFuncAttributeMaxDynamicSharedMemorySize, GEMM_SMEM);
    cudaFuncSetAttribute(gemm_mma<0,0,1>, cudaFuncAttributeMaxDynamicSharedMemorySize, GEMM_SMEM);
    cudaFuncSetAttribute(gemm_mma<0,0,2>, cudaFuncAttributeMaxDynamicSharedMemorySize, GEMM_SMEM);
    cudaFuncSetAttribute(gemm_mma<1,1,0>, cudaFuncAttributeMaxDynamicSharedMemorySize, GEMM_SMEM);

    dim3 tb(32, 8);

    // 1. LN1 -> split
    ln_e128_split<<<BT, 128>>>(X, ln1g, ln1b, xnh, xnl);

    // 2. weight transposes + splits
    transpose_split<<<dim3(E/32, E/32, H), tb>>>(Wq, wqth, wqtl, E, E);
    transpose_split<<<dim3(E/32, E/32, H), tb>>>(Wk, wkth, wktl, E, E);
    transpose_split<<<dim3(E/32, E/32, H), tb>>>(Wv, wvth, wvtl, E, E);
    transpose_split<<<dim3(FF/32, DD/32, 1), tb>>>(W1, w1th, w1tl, DD, FF);
    transpose_split<<<dim3(E/32, FF/32, 1), tb>>>(W2, w2th, w2tl, FF, E);

    // 3. QKV projections (per b,h batch; A shared across h)
    dim3 gqkv(1, T/128, BH);
    gemm_mma<0,1,0><<<gqkv, 256, GEMM_SMEM>>>(xnh, xnl, wqth, wqtl, bq,
        (float*)0, qh, ql, E, E, H, (long)T*E, H, (long)E*E, (long)E, (long)T*E, 1.0f);
    gemm_mma<0,1,0><<<gqkv, 256, GEMM_SMEM>>>(xnh, xnl, wkth, wktl, bk,
        (float*)0, kh, kl, E, E, H, (long)T*E, H, (long)E*E, (long)E, (long)T*E, 1.0f);
    gemm_mma<0,0,0><<<gqkv, 256, GEMM_SMEM>>>(xnh, xnl, wvth, wvtl, bv,
        v, (bf*)0, (bf*)0, E, E, H, (long)T*E, H, (long)E*E, (long)E, (long)T*E, 1.0f);

    // 4. v -> v^T split  [z][T][E] -> [z][E][T]
    transpose_split<<<dim3(E/32, T/32, BH), tb>>>(v, vth, vtl, T, E);

    // 5. scores = q@k^T / sqrt(E)  (skip fully-upper blocks)
    dim3 gsc(T/128, T/128, BH);
    gemm_mma<0,0,1><<<gsc, 256, GEMM_SMEM>>>(qh, ql, kh, kl, (const float*)0,
        s, (bf*)0, (bf*)0, T, E, 1, (long)T*E, BH, (long)T*E, 0, (long)T*T,
        0.08838834764831843f);

    // 6. query-axis softmax -> split bf16 attn
    colsoftmax<<<dim3(T/256, BH), 256>>>(s, ath, atl);

    // 7. out = attn @ v  (K clamped causally)
    dim3 gav(1, T/128, BH);
    gemm_mma<0,0,2><<<gav, 256, GEMM_SMEM>>>(ath, atl, vth, vtl, (const float*)0,
        att, (bf*)0, (bf*)0, E, T, 1, (long)T*T, BH, (long)E*T, 0, (long)T*E, 1.0f);

    // 8. concat + LN2 -> split
    ln_gather_split<<<BT, 256>>>(att, ln2g, ln2b, hnh, hnl);

    // 9. MLP1 + GELU -> split mid
    dim3 g1(FF/128, BT/128, 1);
    gemm_mma<1,1,0><<<g1, 256, GEMM_SMEM>>>(hnh, hnl, w1th, w1tl, b1,
        (float*)0, midh, midl, FF, DD, 1, 0, 1, 0, 0, 0, 1.0f);

    // 10. MLP2 -> out
    dim3 g2(1, BT/128, 1);
    gemm_mma<0,0,0><<<g2, 256, GEMM_SMEM>>>(midh, midl, w2th, w2tl, b2,
        out, (bf*)0, (bf*)0, E, FF, 1, 0, 1, 0, 0, 0, 1.0f);
}

// round 8
// speedup vs baseline: 2.0644x; 1.0112x over previous
#include <cuda_runtime.h>
#include <cuda_bf16.h>
#include <math.h>
#include <stdint.h>

#define Bsz 4
#define T   2048
#define E   128
#define H   8
#define DD  1024
#define FF  4096
#define BT  8192
#define BH  32

typedef __nv_bfloat16 bf;

// ---------------- scratch (device globals; no allocation allowed) -----------
__device__ __align__(16) bf    g_xnh[BT*E],  g_xnl[BT*E];
__device__ __align__(16) bf    g_wqth[H*E*E], g_wqtl[H*E*E];
__device__ __align__(16) bf    g_wkth[H*E*E], g_wktl[H*E*E];
__device__ __align__(16) bf    g_wvth[H*E*E], g_wvtl[H*E*E];
__device__ __align__(16) bf    g_qh[BH*T*E], g_ql[BH*T*E];
__device__ __align__(16) bf    g_kh[BH*T*E], g_kl[BH*T*E];
__device__ __align__(16) float g_v [BH*T*E];
__device__ __align__(16) bf    g_vth[BH*E*T], g_vtl[BH*E*T];
__device__ __align__(16) float g_s [134217728];               // BH*T*T fp32
__device__ __align__(16) bf    g_ath[134217728], g_atl[134217728];
__device__ __align__(16) float g_att[BH*T*E];
__device__ __align__(16) bf    g_hnh[BT*DD], g_hnl[BT*DD];
__device__ __align__(16) bf    g_w1th[FF*DD], g_w1tl[FF*DD];
__device__ __align__(16) bf    g_w2th[E*FF],  g_w2tl[E*FF];
__device__ __align__(16) bf    g_midh[(size_t)BT*FF], g_midl[(size_t)BT*FF];

// ---------------- helpers ---------------------------------------------------
__device__ __forceinline__ uint32_t smem_u32(const void* p) {
    uint32_t a;
    asm("{ .reg .u64 t; cvta.to.shared.u64 t, %1; cvt.u32.u64 %0, t; }"
        : "=r"(a) : "l"(p));
    return a;
}
__device__ __forceinline__ void cpa16(uint32_t dst, const void* src) {
    asm volatile("cp.async.cg.shared.global [%0], [%1], 16;"
                 :: "r"(dst), "l"(src) : "memory");
}
__device__ __forceinline__ void ldm4(uint32_t* r, uint32_t addr) {
    asm volatile("ldmatrix.sync.aligned.m8n8.x4.shared.b16 {%0,%1,%2,%3}, [%4];"
                 : "=r"(r[0]), "=r"(r[1]), "=r"(r[2]), "=r"(r[3]) : "r"(addr));
}
__device__ __forceinline__ void mma16816(float* c, const uint32_t* a, const uint32_t* b) {
    asm volatile(
        "mma.sync.aligned.m16n8k16.row.col.f32.bf16.bf16.f32 "
        "{%0,%1,%2,%3}, {%4,%5,%6,%7}, {%8,%9}, {%0,%1,%2,%3};\n"
        : "+f"(c[0]), "+f"(c[1]), "+f"(c[2]), "+f"(c[3])
        : "r"(a[0]), "r"(a[1]), "r"(a[2]), "r"(a[3]), "r"(b[0]), "r"(b[1]));
}
__device__ __forceinline__ void split_bf16(float x, bf& h, bf& l) {
    h = __float2bfloat16_rn(x);
    l = __float2bfloat16_rn(x - __bfloat162float(h));
}
__device__ __forceinline__ unsigned pack2(bf a, bf b) {
    return (unsigned)__bfloat16_as_ushort(a) | ((unsigned)__bfloat16_as_ushort(b) << 16);
}
__device__ __forceinline__ float gelu_exact(float x) {
    return 0.5f * x * (1.0f + erff(x * 0.70710678118654752440f));
}

// ============================================================================
// BIG split-bf16 HMMA GEMM: CTA tile 256x128, 8 warps (4x2), warp tile 64x64,
// 3-stage cp.async pipeline, k-chunk 32.
//   C[256x128 tile] = alpha * (A @ B^T) (+bias) (EPI==1: gelu)
//  A: [M,K] K-major split bf16 (Ah,Al);  B: [N,K] K-major split bf16 (Bh,Bl)
//  OUTS: 0 -> fp32 C ; 1 -> split bf16 (Ch,Cl)
//  CAUSAL: 0 none, 1 skip block when m0+256<=n0, 2 clamp K to m0+256
//  batch z: A += (z/divA)*sA ; B,bias += (z%modB)*sB/sBias ; C += z*sC
//  K (and kEnd) multiples of 32; M mult of 256, N mult of 128.
// Smem per stage: rows [0,256)=Ah, [256,512)=Al, [512,640)=Bh, [640,768)=Bl,
// each row padded to 40 bf16 (80B) -> ldmatrix conflict-free.
// ============================================================================
#define STAGE_B   (768 * 40 * 2)            // 61440 bytes per stage
#define GEMM2_SMEM (3 * STAGE_B)            // 184320 bytes

template<int EPI, int OUTS, int CAUSAL>
__global__ void __launch_bounds__(256, 1) gemm_mma256(
    const bf* __restrict__ Ahg, const bf* __restrict__ Alg,
    const bf* __restrict__ Bhg, const bf* __restrict__ Blg,
    const float* __restrict__ bias,
    float* __restrict__ C, bf* __restrict__ Ch, bf* __restrict__ Cl,
    int N, int K, int divA, long sA, int modB, long sB, long sBias, long sC,
    float alpha)
{
    extern __shared__ __align__(16) bf sm[];
    const int tid  = threadIdx.x;
    const int wid  = tid >> 5, lane = tid & 31;
    const int wm   = wid >> 1;           // warp row (4)  -> 64 rows each
    const int wn   = wid & 1;            // warp col (2)  -> 64 cols each
    const int m0   = blockIdx.y * 256, n0 = blockIdx.x * 128, bz = blockIdx.z;
    if (CAUSAL == 1 && m0 + 256 <= n0) return;

    const uint32_t sbase = smem_u32(sm);

    const bf* A0 = Ahg + (long)(bz / divA) * sA + (long)m0 * K;
    const bf* A1 = Alg + (long)(bz / divA) * sA + (long)m0 * K;
    const bf* B0 = Bhg + (long)(bz % modB) * sB + (long)n0 * K;
    const bf* B1 = Blg + (long)(bz % modB) * sB + (long)n0 * K;

    int kEnd = K;
    if (CAUSAL == 2) { int ke = m0 + 256; kEnd = ke < K ? ke : K; }
    const int nch = kEnd >> 5;           // chunks of 32

    // 3072 16B-chunks per stage: A0 [0,1024), A1 [1024,2048), B0 [2048,2560), B1 [2560,3072)
    auto loadStage = [&](int st, int k0) {
        #pragma unroll
        for (int i = 0; i < 12; ++i) {
            int idx = tid + i * 256;     // 0..3071
            const bf* srcB; int matrow;
            if (idx < 1024)      { int r = idx >> 2;          srcB = A0 + (long)r * K; matrow = r; }
            else if (idx < 2048) { int r = (idx - 1024) >> 2; srcB = A1 + (long)r * K; matrow = 256 + r; }
            else if (idx < 2560) { int r = (idx - 2048) >> 2; srcB = B0 + (long)r * K; matrow = 512 + r; }
            else                 { int r = (idx - 2560) >> 2; srcB = B1 + (long)r * K; matrow = 640 + r; }
            int seg = idx & 3;
            uint32_t dst = sbase + (uint32_t)(st * STAGE_B)
                         + (uint32_t)((matrow * 40 + seg * 8) * 2);
            cpa16(dst, srcB + k0 + seg * 8);
        }
        asm volatile("cp.async.commit_group;" ::: "memory");
    };

    float acc[4][8][4];
    #pragma unroll
    for (int a = 0; a < 4; ++a)
        #pragma unroll
        for (int b = 0; b < 8; ++b)
            #pragma unroll
            for (int c = 0; c < 4; ++c) acc[a][b][c] = 0.f;

    loadStage(0, 0);
    loadStage(1, 32);

    const int lm = lane & 15, lk = lane >> 4;            // A ldmatrix addressing
    const int bn = (lane & 7) | ((lane >> 1) & 8);       // B ldmatrix addressing
    const int bk = (lane >> 3) & 1;

    for (int c = 0; c < nch; ++c) {
        if (c < nch - 1) {
            asm volatile("cp.async.wait_group 1;" ::: "memory");
        } else {
            asm volatile("cp.async.wait_group 0;" ::: "memory");
        }
        __syncthreads();
        if (c + 2 < nch) loadStage((c + 2) % 3, (c + 2) << 5);

        const uint32_t stb = sbase + (uint32_t)((c % 3) * STAGE_B);
        #pragma unroll
        for (int ks = 0; ks < 32; ks += 16) {
            uint32_t ah[4][4], al[4][4], bh[4][4], bl[4][4];
            #pragma unroll
            for (int mt = 0; mt < 4; ++mt) {
                int row = wm * 64 + mt * 16 + lm, col = ks + lk * 8;
                ldm4(ah[mt], stb + (uint32_t)(((      row) * 40 + col) * 2));
                ldm4(al[mt], stb + (uint32_t)(((256 + row) * 40 + col) * 2));
            }
            #pragma unroll
            for (int p = 0; p < 4; ++p) {
                int row = wn * 64 + p * 16 + bn, col = ks + bk * 8;
                ldm4(bh[p], stb + (uint32_t)(((512 + row) * 40 + col) * 2));
                ldm4(bl[p], stb + (uint32_t)(((640 + row) * 40 + col) * 2));
            }
            #pragma unroll
            for (int mt = 0; mt < 4; ++mt)
                #pragma unroll
                for (int nt = 0; nt < 8; ++nt) {
                    const uint32_t* Bh = &bh[nt >> 1][(nt & 1) * 2];
                    const uint32_t* Bl = &bl[nt >> 1][(nt & 1) * 2];
                    mma16816(acc[mt][nt], ah[mt], Bh);
                    mma16816(acc[mt][nt], ah[mt], Bl);
                    mma16816(acc[mt][nt], al[mt], Bh);
                }
        }
        __syncthreads();
    }

    // ------------------------- epilogue -------------------------
    const int l4 = lane >> 2, l2 = (lane & 3) * 2;
    const float* bp = bias ? bias + (long)(bz % modB) * sBias : (const float*)0;
    #pragma unroll
    for (int mt = 0; mt < 4; ++mt) {
        #pragma unroll
        for (int nt = 0; nt < 8; ++nt) {
            int col = n0 + wn * 64 + nt * 8 + l2;
            float b0 = 0.f, b1 = 0.f;
            if (bp) { b0 = __ldg(&bp[col]); b1 = __ldg(&bp[col + 1]); }
            #pragma unroll
            for (int hrow = 0; hrow < 2; ++hrow) {
                int r = m0 + wm * 64 + mt * 16 + hrow * 8 + l4;
                float v0 = acc[mt][nt][hrow * 2 + 0] * alpha + b0;
                float v1 = acc[mt][nt][hrow * 2 + 1] * alpha + b1;
                if (EPI == 1) { v0 = gelu_exact(v0); v1 = gelu_exact(v1); }
                long off = (long)bz * sC + (long)r * N + col;
                if (OUTS == 0) {
                    *(float2*)(C + off) = make_float2(v0, v1);
                } else {
                    bf h0, l0, h1, l1;
                    split_bf16(v0, h0, l0);
                    split_bf16(v1, h1, l1);
                    *(unsigned*)(Ch + off) = pack2(h0, h1);
                    *(unsigned*)(Cl + off) = pack2(l0, l1);
                }
            }
        }
    }
}

// ============================================================================
// Small split-bf16 HMMA GEMM (128x128, 8 warps 2x4, warp 64x32) — kept for
// MLP2 (N=128 -> needs more CTAs in M). Same semantics as gemm_mma256.
// ============================================================================
#define GEMM_SMEM (2 * 4 * 128 * 40 * 2)   // 81920 bytes

template<int EPI, int OUTS, int CAUSAL>
__global__ void __launch_bounds__(256, 1) gemm_mma(
    const bf* __restrict__ Ahg, const bf* __restrict__ Alg,
    const bf* __restrict__ Bhg, const bf* __restrict__ Blg,
    const float* __restrict__ bias,
    float* __restrict__ C, bf* __restrict__ Ch, bf* __restrict__ Cl,
    int N, int K, int divA, long sA, int modB, long sB, long sBias, long sC,
    float alpha)
{
    extern __shared__ __align__(16) bf sm[];
    const int tid  = threadIdx.x;
    const int wid  = tid >> 5, lane = tid & 31;
    const int wm   = wid & 1;
    const int wn   = wid >> 1;
    const int m0   = blockIdx.y * 128, n0 = blockIdx.x * 128, bz = blockIdx.z;
    if (CAUSAL == 1 && m0 + 128 <= n0) return;

    const uint32_t sbase = smem_u32(sm);

    const bf* A0 = Ahg + (long)(bz / divA) * sA + (long)m0 * K;
    const bf* A1 = Alg + (long)(bz / divA) * sA + (long)m0 * K;
    const bf* B0 = Bhg + (long)(bz % modB) * sB + (long)n0 * K;
    const bf* B1 = Blg + (long)(bz % modB) * sB + (long)n0 * K;

    int kEnd = K;
    if (CAUSAL == 2) { int ke = m0 + 128; kEnd = ke < K ? ke : K; }
    const int nch = kEnd >> 5;

    auto loadStage = [&](int st, int k0) {
        #pragma unroll
        for (int i = 0; i < 8; ++i) {
            int idx = tid + i * 256;
            int mat = idx >> 9;
            int rem = idx & 511;
            int row = rem >> 2;
            int seg = rem & 3;
            const bf* src = (mat == 0 ? A0 : mat == 1 ? A1 : mat == 2 ? B0 : B1)
                            + (long)row * K + k0 + seg * 8;
            uint32_t dst = sbase + (uint32_t)((((mat)*128 + row) * 40 + seg * 8) * 2)
                                 + (uint32_t)(st * 40960);
            cpa16(dst, src);
        }
        asm volatile("cp.async.commit_group;" ::: "memory");
    };

    float acc[4][4][4];
    #pragma unroll
    for (int a = 0; a < 4; ++a)
        #pragma unroll
        for (int b = 0; b < 4; ++b)
            #pragma unroll
            for (int c = 0; c < 4; ++c) acc[a][b][c] = 0.f;

    loadStage(0, 0);

    const int lm = lane & 15, lk = lane >> 4;
    const int bn = (lane & 7) | ((lane >> 1) & 8);
    const int bk = (lane >> 3) & 1;

    for (int c = 0; c < nch; ++c) {
        int st = c & 1;
        if (c + 1 < nch) {
            loadStage(st ^ 1, (c + 1) << 5);
            asm volatile("cp.async.wait_group 1;" ::: "memory");
        } else {
            asm volatile("cp.async.wait_group 0;" ::: "memory");
        }
        __syncthreads();

        const uint32_t stb = sbase + (uint32_t)(st * 40960);
        #pragma unroll
        for (int ks = 0; ks < 32; ks += 16) {
            uint32_t ah[4][4], al[4][4], bh[2][4], bl[2][4];
            #pragma unroll
            for (int mt = 0; mt < 4; ++mt) {
                int row = wm * 64 + mt * 16 + lm, col = ks + lk * 8;
                ldm4(ah[mt], stb + (uint32_t)(((0 * 128 + row) * 40 + col) * 2));
                ldm4(al[mt], stb + (uint32_t)(((1 * 128 + row) * 40 + col) * 2));
            }
            #pragma unroll
            for (int p = 0; p < 2; ++p) {
                int row = wn * 32 + p * 16 + bn, col = ks + bk * 8;
                ldm4(bh[p], stb + (uint32_t)(((2 * 128 + row) * 40 + col) * 2));
                ldm4(bl[p], stb + (uint32_t)(((3 * 128 + row) * 40 + col) * 2));
            }
            #pragma unroll
            for (int mt = 0; mt < 4; ++mt)
                #pragma unroll
                for (int nt = 0; nt < 4; ++nt) {
                    const uint32_t* Bh = &bh[nt >> 1][(nt & 1) * 2];
                    const uint32_t* Bl = &bl[nt >> 1][(nt & 1) * 2];
                    mma16816(acc[mt][nt], ah[mt], Bh);
                    mma16816(acc[mt][nt], ah[mt], Bl);
                    mma16816(acc[mt][nt], al[mt], Bh);
                }
        }
        __syncthreads();
    }

    const int l4 = lane >> 2, l2 = (lane & 3) * 2;
    const float* bp = bias ? bias + (long)(bz % modB) * sBias : (const float*)0;
    #pragma unroll
    for (int mt = 0; mt < 4; ++mt) {
        #pragma unroll
        for (int nt = 0; nt < 4; ++nt) {
            int col = n0 + wn * 32 + nt * 8 + l2;
            float b0 = 0.f, b1 = 0.f;
            if (bp) { b0 = __ldg(&bp[col]); b1 = __ldg(&bp[col + 1]); }
            #pragma unroll
            for (int hrow = 0; hrow < 2; ++hrow) {
                int r = m0 + wm * 64 + mt * 16 + hrow * 8 + l4;
                float v0 = acc[mt][nt][hrow * 2 + 0] * alpha + b0;
                float v1 = acc[mt][nt][hrow * 2 + 1] * alpha + b1;
                if (EPI == 1) { v0 = gelu_exact(v0); v1 = gelu_exact(v1); }
                long off = (long)bz * sC + (long)r * N + col;
                if (OUTS == 0) {
                    *(float2*)(C + off) = make_float2(v0, v1);
                } else {
                    bf h0, l0, h1, l1;
                    split_bf16(v0, h0, l0);
                    split_bf16(v1, h1, l1);
                    *(unsigned*)(Ch + off) = pack2(h0, h1);
                    *(unsigned*)(Cl + off) = pack2(l0, l1);
                }
            }
        }
    }
}

// ============================================================================
// LayerNorm over E=128 -> split bf16 out
// ============================================================================
__global__ void ln_e128_split(const float* __restrict__ X, const float* __restrict__ g,
                              const float* __restrict__ b,
                              bf* __restrict__ Oh, bf* __restrict__ Ol)
{
    const int row = blockIdx.x, tid = threadIdx.x;
    float x = X[(size_t)row * 128 + tid];
    float s1 = x, s2 = x * x;
    #pragma unroll
    for (int o = 16; o > 0; o >>= 1) {
        s1 += __shfl_xor_sync(0xffffffffu, s1, o);
        s2 += __shfl_xor_sync(0xffffffffu, s2, o);
    }
    __shared__ float r1[4], r2[4];
    if ((tid & 31) == 0) { r1[tid >> 5] = s1; r2[tid >> 5] = s2; }
    __syncthreads();
    s1 = r1[0] + r1[1] + r1[2] + r1[3];
    s2 = r2[0] + r2[1] + r2[2] + r2[3];
    float mu  = s1 * (1.0f / 128.0f);
    float var = s2 * (1.0f / 128.0f) - mu * mu;
    float rs  = rsqrtf(var + 1e-5f);
    float o = (x - mu) * rs * g[tid] + b[tid];
    bf h, l; split_bf16(o, h, l);
    Oh[(size_t)row * 128 + tid] = h;
    Ol[(size_t)row * 128 + tid] = l;
}

// ============================================================================
// Gather heads [B,H,T,E] -> [B,T,D] + LayerNorm over D=1024 -> split bf16
// ============================================================================
__global__ void ln_gather_split(const float* __restrict__ att, const float* __restrict__ g,
                                const float* __restrict__ b,
                                bf* __restrict__ Oh, bf* __restrict__ Ol)
{
    const int row = blockIdx.x;
    const int bb = row >> 11, t = row & 2047;
    const int tid = threadIdx.x;
    const int d0 = tid * 4, h = d0 >> 7, e = d0 & 127;

    float4 v = *(const float4*)&att[((size_t)(bb * H + h) * T + t) * E + e];
    float s1 = v.x + v.y + v.z + v.w;
    float s2 = v.x*v.x + v.y*v.y + v.z*v.z + v.w*v.w;
    #pragma unroll
    for (int o = 16; o > 0; o >>= 1) {
        s1 += __shfl_xor_sync(0xffffffffu, s1, o);
        s2 += __shfl_xor_sync(0xffffffffu, s2, o);
    }
    __shared__ float r1[8], r2[8];
    if ((tid & 31) == 0) { r1[tid >> 5] = s1; r2[tid >> 5] = s2; }
    __syncthreads();
    s1 = 0.f; s2 = 0.f;
    #pragma unroll
    for (int i = 0; i < 8; i++) { s1 += r1[i]; s2 += r2[i]; }
    float mu  = s1 * (1.0f / 1024.0f);
    float var = s2 * (1.0f / 1024.0f) - mu * mu;
    float rs  = rsqrtf(var + 1e-5f);

    float4 gg = *(const float4*)&g[d0];
    float4 bv = *(const float4*)&b[d0];
    float o0 = (v.x - mu) * rs * gg.x + bv.x;
    float o1 = (v.y - mu) * rs * gg.y + bv.y;
    float o2 = (v.z - mu) * rs * gg.z + bv.z;
    float o3 = (v.w - mu) * rs * gg.w + bv.w;
    bf h0,l0,h1,l1,h2,l2,h3,l3;
    split_bf16(o0,h0,l0); split_bf16(o1,h1,l1);
    split_bf16(o2,h2,l2); split_bf16(o3,h3,l3);
    size_t off = (size_t)row * 1024 + d0;
    *(uint2*)&Oh[off] = make_uint2(pack2(h0,h1), pack2(h2,h3));
    *(uint2*)&Ol[off] = make_uint2(pack2(l0,l1), pack2(l2,l3));
}

// ============================================================================
// Transpose + split:  in fp32 [z][R][Cc]  ->  out split bf16 [z][Cc][R]
// grid (Cc/32, R/32, z), block (32,8)
// ============================================================================
__global__ void transpose_split(const float* __restrict__ in,
                                bf* __restrict__ oh, bf* __restrict__ ol,
                                int R, int Cc)
{
    __shared__ float tle[32][33];
    int z = blockIdx.z;
    const float* ip = in + (size_t)z * R * Cc;
    size_t ob = (size_t)z * R * Cc;
    int r0 = blockIdx.y * 32, c0 = blockIdx.x * 32;
    int tx = threadIdx.x, ty = threadIdx.y;
    #pragma unroll
    for (int i = ty; i < 32; i += 8)
        tle[i][tx] = ip[(size_t)(r0 + i) * Cc + c0 + tx];
    __syncthreads();
    #pragma unroll
    for (int i = ty; i < 32; i += 8) {
        float v = tle[tx][i];
        bf h, l; split_bf16(v, h, l);
        size_t o = ob + (size_t)(c0 + i) * R + r0 + tx;
        oh[o] = h; ol[o] = l;
    }
}

// ============================================================================
// Softmax over the QUERY axis t (per column s), causal region t >= s.
// Single online read pass (max+sum), then exp/normalize write pass.
// Writes split-bf16 attn; zeros cover the band t in [s-255, s) that AV reads
// (AV uses 256-row blocks with K clamped to m0+256).
// ============================================================================
__global__ void colsoftmax(const float* __restrict__ S,
                           bf* __restrict__ Oh, bf* __restrict__ Ol)
{
    int z = blockIdx.y;
    const float* P = S + (size_t)z * T * T;
    bf* oh = Oh + (size_t)z * T * T;
    bf* ol = Ol + (size_t)z * T * T;
    int s = blockIdx.x * blockDim.x + threadIdx.x;

    float m = -3.4e38f, sum = 0.f;
    for (int t = s; t < T; ++t) {
        float v = P[(size_t)t * T + s];
        if (v <= m) {
            sum += __expf(v - m);
        } else {
            sum = sum * __expf(m - v) + 1.0f;
            m = v;
        }
    }
    float inv = 1.0f / sum;
    int t0 = s - 255; if (t0 < 0) t0 = 0;
    for (int t = t0; t < T; ++t) {
        float o = 0.0f;
        if (t >= s) o = __expf(P[(size_t)t * T + s] - m) * inv;
        bf h, l; split_bf16(o, h, l);
        oh[(size_t)t * T + s] = h;
        ol[(size_t)t * T + s] = l;
    }
}

// ============================================================================
// Host launcher
// ============================================================================
extern "C" void kernel_launch(void* const* d_in, const int* in_sizes, int n_in,
                              void* d_out, int out_size)
{
    const float* X    = (const float*)d_in[0];
    const float* ln1g = (const float*)d_in[1];
    const float* ln1b = (const float*)d_in[2];
    const float* Wq   = (const float*)d_in[3];
    const float* bq   = (const float*)d_in[4];
    const float* Wk   = (const float*)d_in[5];
    const float* bk   = (const float*)d_in[6];
    const float* Wv   = (const float*)d_in[7];
    const float* bv   = (const float*)d_in[8];
    const float* ln2g = (const float*)d_in[9];
    const float* ln2b = (const float*)d_in[10];
    const float* W1   = (const float*)d_in[11];
    const float* b1   = (const float*)d_in[12];
    const float* W2   = (const float*)d_in[13];
    const float* b2   = (const float*)d_in[14];
    float* out = (float*)d_out;

    bf *xnh,*xnl,*wqth,*wqtl,*wkth,*wktl,*wvth,*wvtl,*qh,*ql,*kh,*kl;
    bf *vth,*vtl,*ath,*atl,*hnh,*hnl,*w1th,*w1tl,*w2th,*w2tl,*midh,*midl;
    float *v, *s, *att;
    cudaGetSymbolAddress((void**)&xnh, g_xnh);   cudaGetSymbolAddress((void**)&xnl, g_xnl);
    cudaGetSymbolAddress((void**)&wqth, g_wqth); cudaGetSymbolAddress((void**)&wqtl, g_wqtl);
    cudaGetSymbolAddress((void**)&wkth, g_wkth); cudaGetSymbolAddress((void**)&wktl, g_wktl);
    cudaGetSymbolAddress((void**)&wvth, g_wvth); cudaGetSymbolAddress((void**)&wvtl, g_wvtl);
    cudaGetSymbolAddress((void**)&qh, g_qh);     cudaGetSymbolAddress((void**)&ql, g_ql);
    cudaGetSymbolAddress((void**)&kh, g_kh);     cudaGetSymbolAddress((void**)&kl, g_kl);
    cudaGetSymbolAddress((void**)&v, g_v);
    cudaGetSymbolAddress((void**)&vth, g_vth);   cudaGetSymbolAddress((void**)&vtl, g_vtl);
    cudaGetSymbolAddress((void**)&s, g_s);
    cudaGetSymbolAddress((void**)&ath, g_ath);   cudaGetSymbolAddress((void**)&atl, g_atl);
    cudaGetSymbolAddress((void**)&att, g_att);
    cudaGetSymbolAddress((void**)&hnh, g_hnh);   cudaGetSymbolAddress((void**)&hnl, g_hnl);
    cudaGetSymbolAddress((void**)&w1th, g_w1th); cudaGetSymbolAddress((void**)&w1tl, g_w1tl);
    cudaGetSymbolAddress((void**)&w2th, g_w2th); cudaGetSymbolAddress((void**)&w2tl, g_w2tl);
    cudaGetSymbolAddress((void**)&midh, g_midh); cudaGetSymbolAddress((void**)&midl, g_midl);

    cudaFuncSetAttribute(gemm_mma256<0,1,0>, cudaFuncAttributeMaxDynamicSharedMemorySize, GEMM2_SMEM);
    cudaFuncSetAttribute(gemm_mma256<0,0,0>, cudaFuncAttributeMaxDynamicSharedMemorySize, GEMM2_SMEM);
    cudaFuncSetAttribute(gemm_mma256<0,0,1>, cudaFuncAttributeMaxDynamicSharedMemorySize, GEMM2_SMEM);
    cudaFuncSetAttribute(gemm_mma256<0,0,2>, cudaFuncAttributeMaxDynamicSharedMemorySize, GEMM2_SMEM);
    cudaFuncSetAttribute(gemm_mma256<1,1,0>, cudaFuncAttributeMaxDynamicSharedMemorySize, GEMM2_SMEM);
    cudaFuncSetAttribute(gemm_mma<0,0,0>,    cudaFuncAttributeMaxDynamicSharedMemorySize, GEMM_SMEM);

    dim3 tb(32, 8);

    // 1. LN1 -> split
    ln_e128_split<<<BT, 128>>>(X, ln1g, ln1b, xnh, xnl);

    // 2. weight transposes + splits
    transpose_split<<<dim3(E/32, E/32, H), tb>>>(Wq, wqth, wqtl, E, E);
    transpose_split<<<dim3(E/32, E/32, H), tb>>>(Wk, wkth, wktl, E, E);
    transpose_split<<<dim3(E/32, E/32, H), tb>>>(Wv, wvth, wvtl, E, E);
    transpose_split<<<dim3(FF/32, DD/32, 1), tb>>>(W1, w1th, w1tl, DD, FF);
    transpose_split<<<dim3(E/32, FF/32, 1), tb>>>(W2, w2th, w2tl, FF, E);

    // 3. QKV projections (per b,h batch; A shared across h)
    dim3 gqkv(1, T/256, BH);
    gemm_mma256<0,1,0><<<gqkv, 256, GEMM2_SMEM>>>(xnh, xnl, wqth, wqtl, bq,
        (float*)0, qh, ql, E, E, H, (long)T*E, H, (long)E*E, (long)E, (long)T*E, 1.0f);
    gemm_mma256<0,1,0><<<gqkv, 256, GEMM2_SMEM>>>(xnh, xnl, wkth, wktl, bk,
        (float*)0, kh, kl, E, E, H, (long)T*E, H, (long)E*E, (long)E, (long)T*E, 1.0f);
    gemm_mma256<0,0,0><<<gqkv, 256, GEMM2_SMEM>>>(xnh, xnl, wvth, wvtl, bv,
        v, (bf*)0, (bf*)0, E, E, H, (long)T*E, H, (long)E*E, (long)E, (long)T*E, 1.0f);

    // 4. v -> v^T split  [z][T][E] -> [z][E][T]
    transpose_split<<<dim3(E/32, T/32, BH), tb>>>(v, vth, vtl, T, E);

    // 5. scores = q@k^T / sqrt(E)  (skip fully-upper blocks)
    dim3 gsc(T/128, T/256, BH);
    gemm_mma256<0,0,1><<<gsc, 256, GEMM2_SMEM>>>(qh, ql, kh, kl, (const float*)0,
        s, (bf*)0, (bf*)0, T, E, 1, (long)T*E, BH, (long)T*E, 0, (long)T*T,
        0.08838834764831843f);

    // 6. query-axis softmax -> split bf16 attn
    colsoftmax<<<dim3(T/256, BH), 256>>>(s, ath, atl);

    // 7. out = attn @ v  (K clamped causally at m0+256)
    dim3 gav(1, T/256, BH);
    gemm_mma256<0,0,2><<<gav, 256, GEMM2_SMEM>>>(ath, atl, vth, vtl, (const float*)0,
        att, (bf*)0, (bf*)0, E, T, 1, (long)T*T, BH, (long)E*T, 0, (long)T*E, 1.0f);

    // 8. concat + LN2 -> split
    ln_gather_split<<<BT, 256>>>(att, ln2g, ln2b, hnh, hnl);

    // 9. MLP1 + GELU -> split mid
    dim3 g1(FF/128, BT/256, 1);
    gemm_mma256<1,1,0><<<g1, 256, GEMM2_SMEM>>>(hnh, hnl, w1th, w1tl, b1,
        (float*)0, midh, midl, FF, DD, 1, 0, 1, 0, 0, 0, 1.0f);

    // 10. MLP2 -> out (128x128 kernel for grid coverage: 64 CTAs)
    dim3 g2(1, BT/128, 1);
    gemm_mma<0,0,0><<<g2, 256, GEMM_SMEM>>>(midh, midl, w2th, w2tl, b2,
        out, (bf*)0, (bf*)0, E, FF, 1, 0, 1, 0, 0, 0, 1.0f);
}